// round 16
// baseline (speedup 1.0000x reference)
#include <cuda_runtime.h>
#include <cuda_fp16.h>
#include <mma.h>
#include <math.h>
#include <cstdint>

using namespace nvcuda;

#define NN 50000
#define NE 800000
#define ET (NE + NN)
#define C1 256
#define CH 128
#define FCH 64
#define NEG_SLOPE 0.2f
#define EPS 1e-16f

// ---------------- device scratch ----------------
__device__ int   g_is64;
__device__ int   g_deg[NN];
__device__ int   g_dinc[NN];
__device__ int   g_bsum[64];
__device__ int   g_rowstart[NN + 1];
__device__ int   g_cursor[NN];
__device__ int   g_srcs[ET];
__device__ int2  g_edge2[NE];
__device__ __half g_xh[(size_t)NN * CH];    // fp16 x
__device__ __half g_w1h[CH * C1];           // fp16 W1
__device__ __half g_w2h[C1 * CH];           // fp16 W2
__device__ __half g_axg[(size_t)NN * C1];   // fp16 attention-aggregated x (2 heads)
__device__ __half g_h2h[(size_t)NN * CH];   // fp16 h2 (gather-only)
__device__ __half g_o1h[(size_t)NN * C1];   // fp16 out1
__device__ float g_a1s[NN * 2], g_a1d[NN * 2];
__device__ float g_a2s[NN],     g_a2d[NN];
__device__ float g_u1s[256], g_u1d[256];    // W1 @ as1 / ad1 (head-major: [h*128+k])
__device__ float g_u2s[256], g_u2d[256];    // W2 @ as2 / ad2

// ---------------- helpers ----------------
__device__ __forceinline__ float warpSum(float v) {
    #pragma unroll
    for (int o = 16; o; o >>= 1) v += __shfl_xor_sync(0xffffffffu, v, o);
    return v;
}
__device__ __forceinline__ int warpSumI(int v) {
    #pragma unroll
    for (int o = 16; o; o >>= 1) v += __shfl_xor_sync(0xffffffffu, v, o);
    return v;
}
__device__ __forceinline__ float lrelu(float x) { return x > 0.f ? x : NEG_SLOPE * x; }
__device__ __forceinline__ float elu1(float x)  { return x > 0.f ? x : (__expf(x) - 1.0f); }
__device__ __forceinline__ uint32_t pk2(float a, float b) {
    __half2 h = __floats2half2_rn(a, b);
    return *(uint32_t*)&h;
}

// ---------------- fused pre-kernel: uvec | init | prep ----------------
#define NPREP (NN * CH / 8 + CH * C1 / 8 + C1 * CH / 8)
#define PRE_TOT (16384 + NN + NPREP)

__global__ void k_pre(const int* __restrict__ raw, const float* __restrict__ x,
                      const float* __restrict__ W1, const float* __restrict__ W2,
                      const float* __restrict__ as1, const float* __restrict__ ad1,
                      const float* __restrict__ as2, const float* __restrict__ ad2) {
    int t = blockIdx.x * blockDim.x + threadIdx.x;
    if (t < 16384) {                       // uvec: 512 warps
        int gw = t >> 5, lane = t & 31;
        if (gw < 256) {
            int h = gw >> 7, k = gw & 127;
            float4 w = ((const float4*)(W1 + k * 256 + h * 128))[lane];
            float4 s = ((const float4*)(as1 + h * 128))[lane];
            float4 d = ((const float4*)(ad1 + h * 128))[lane];
            float ps = w.x * s.x + w.y * s.y + w.z * s.z + w.w * s.w;
            float pd = w.x * d.x + w.y * d.y + w.z * d.z + w.w * d.w;
            ps = warpSum(ps); pd = warpSum(pd);
            if (lane == 0) { g_u1s[gw] = ps; g_u1d[gw] = pd; }
        } else {
            int k = gw - 256;
            float4 w = ((const float4*)(W2 + k * 128))[lane];
            float4 s = ((const float4*)as2)[lane];
            float4 d = ((const float4*)ad2)[lane];
            float ps = w.x * s.x + w.y * s.y + w.z * s.z + w.w * s.w;
            float pd = w.x * d.x + w.y * d.y + w.z * d.z + w.w * d.w;
            ps = warpSum(ps); pd = warpSum(pd);
            if (lane == 0) { g_u2s[k] = ps; g_u2d[k] = pd; }
        }
    } else if (t < 16384 + NN) {           // init
        int i = t - 16384;
        g_deg[i] = 0;
        if (i == 0) {
            int ok = 1;
            #pragma unroll
            for (int q = 0; q < 64; q++) ok &= (raw[2 * q + 1] == 0);
            g_is64 = ok;
        }
    } else {                               // prep: fp32 -> fp16
        int idx = t - 16384 - NN;
        const int NX  = NN * CH / 8;
        const int NW1 = CH * C1 / 8;
        const float4* src; uint4* dst;
        if (idx < NX)            { src = (const float4*)x;  dst = (uint4*)g_xh; }
        else if (idx < NX + NW1) { src = (const float4*)W1; dst = (uint4*)g_w1h; idx -= NX; }
        else                     { src = (const float4*)W2; dst = (uint4*)g_w2h; idx -= NX + NW1; }
        float4 a = src[2 * idx], b = src[2 * idx + 1];
        dst[idx] = make_uint4(pk2(a.x, a.y), pk2(a.z, a.w), pk2(b.x, b.y), pk2(b.z, b.w));
    }
}

// ---------------- layer-1 attention dots: a1 = xh . u1 (warp per node) ----------------
__global__ void k_dot1() {
    __shared__ float s_u1s[256], s_u1d[256];
    int tid = threadIdx.x;
    s_u1s[tid] = g_u1s[tid];
    s_u1d[tid] = g_u1d[tid];
    __syncthreads();
    int w = (blockIdx.x * blockDim.x + tid) >> 5;
    int lane = tid & 31;
    if (w >= NN) return;
    uint2 pk = *(const uint2*)(g_xh + (size_t)w * CH + lane * 4);
    float2 f0 = __half22float2(*(const __half2*)&pk.x);
    float2 f1 = __half22float2(*(const __half2*)&pk.y);
    float fv[4] = {f0.x, f0.y, f1.x, f1.y};
    float ps0 = 0.f, pd0 = 0.f, ps1 = 0.f, pd1 = 0.f;
    #pragma unroll
    for (int i = 0; i < 4; i++) {
        int k = lane * 4 + i;
        ps0 += fv[i] * s_u1s[k];       pd0 += fv[i] * s_u1d[k];
        ps1 += fv[i] * s_u1s[128 + k]; pd1 += fv[i] * s_u1d[128 + k];
    }
    ps0 = warpSum(ps0); pd0 = warpSum(pd0);
    ps1 = warpSum(ps1); pd1 = warpSum(pd1);
    if (lane == 0) {
        g_a1s[2 * w] = ps0;     g_a1d[2 * w] = pd0;
        g_a1s[2 * w + 1] = ps1; g_a1d[2 * w + 1] = pd1;
    }
}

// ---------------- CSR build ----------------
__global__ void k_count(const int* __restrict__ raw) {
    int t = blockIdx.x * blockDim.x + threadIdx.x;
    if (t < NE) {
        int s, d;
        if (g_is64) { s = raw[2 * t]; d = raw[2 * (NE + t)]; }
        else        { s = raw[t];     d = raw[NE + t]; }
        g_edge2[t] = make_int2(s, d);
        atomicAdd(&g_deg[d], 1);
    } else if (t < ET) {
        atomicAdd(&g_deg[t - NE], 1);
    }
}
__global__ void k_scanA() {
    __shared__ int wtot[32];
    int t = threadIdx.x, lane = t & 31, wd = t >> 5;
    int i = blockIdx.x * 1024 + t;
    int v = (i < NN) ? g_deg[i] : 0;
    int ws = v;
    #pragma unroll
    for (int off = 1; off < 32; off <<= 1) {
        int y = __shfl_up_sync(0xffffffffu, ws, off);
        if (lane >= off) ws += y;
    }
    if (lane == 31) wtot[wd] = ws;
    __syncthreads();
    if (wd == 0) {
        int tv = wtot[lane];
        #pragma unroll
        for (int off = 1; off < 32; off <<= 1) {
            int y = __shfl_up_sync(0xffffffffu, tv, off);
            if (lane >= off) tv += y;
        }
        wtot[lane] = tv;
        if (lane == 31) g_bsum[blockIdx.x] = tv;
    }
    __syncthreads();
    int woff = wd ? wtot[wd - 1] : 0;
    if (i < NN) g_dinc[i] = woff + ws;
}
__global__ void k_scanC() {
    __shared__ int s_boff;
    int t = threadIdx.x;
    if (t < 32) {
        int b = blockIdx.x;
        int v = (t < b) ? g_bsum[t] : 0;
        if (t + 32 < b) v += g_bsum[t + 32];
        v = warpSumI(v);
        if (t == 0) s_boff = v;
    }
    __syncthreads();
    int boff = s_boff;
    int i = blockIdx.x * 1024 + t;
    if (i < NN) {
        int inc = g_dinc[i] + boff;
        g_rowstart[i + 1] = inc;
        g_cursor[i] = inc - g_deg[i];
    }
    if (i == 0) g_rowstart[0] = 0;
}
__global__ void k_fill() {
    int t = blockIdx.x * blockDim.x + threadIdx.x;
    if (t < NE) {
        int2 e = g_edge2[t];
        int p = atomicAdd(&g_cursor[e.y], 1);
        g_srcs[p] = e.x;
    } else if (t < ET) {
        int n = t - NE;
        int p = atomicAdd(&g_cursor[n], 1);
        g_srcs[p] = n;
    }
}

// ---------------- layer-1 aggregation over x (256B/edge serves BOTH heads) ----------------
__global__ void k_aggX() {
    int tid = threadIdx.x;
    int w = (blockIdx.x * blockDim.x + tid) >> 5;
    int lane = tid & 31;
    if (w >= NN) return;
    int beg = g_rowstart[w], end = g_rowstart[w + 1];
    float ad0 = g_a1d[2 * w], ad1 = g_a1d[2 * w + 1];

    float z0 = 0.f, z1 = 0.f;
    float a0[4] = {0, 0, 0, 0}, a1[4] = {0, 0, 0, 0};
    #pragma unroll 2
    for (int j = beg; j < end; j++) {
        int s = g_srcs[j];
        float2 as = *(const float2*)&g_a1s[2 * s];
        float e0 = __expf(lrelu(as.x + ad0));
        float e1 = __expf(lrelu(as.y + ad1));
        z0 += e0; z1 += e1;
        uint2 pk = *(const uint2*)(g_xh + (size_t)s * CH + lane * 4);
        float2 f0 = __half22float2(*(const __half2*)&pk.x);
        float2 f1 = __half22float2(*(const __half2*)&pk.y);
        a0[0] += e0 * f0.x; a0[1] += e0 * f0.y; a0[2] += e0 * f1.x; a0[3] += e0 * f1.y;
        a1[0] += e1 * f0.x; a1[1] += e1 * f0.y; a1[2] += e1 * f1.x; a1[3] += e1 * f1.y;
    }
    float iz0 = 1.0f / (z0 + EPS), iz1 = 1.0f / (z1 + EPS);
    uint2 o0 = make_uint2(pk2(a0[0] * iz0, a0[1] * iz0), pk2(a0[2] * iz0, a0[3] * iz0));
    uint2 o1 = make_uint2(pk2(a1[0] * iz1, a1[1] * iz1), pk2(a1[2] * iz1, a1[3] * iz1));
    *(uint2*)(g_axg + (size_t)w * C1 + lane * 4)       = o0;
    *(uint2*)(g_axg + (size_t)w * C1 + 128 + lane * 4) = o1;
}

// ---------------- WMMA fp16 GEMM ----------------
// MODE 1: o1 = elu(axg_head @ W1_head + b1)  (per-head cols of axg; fp32 C staging)
// MODE 2: h2 = o1h @ W2                      (K=256; fp16 C staging)
#define PA 136
#define PC 132
#define OFF_A 0
#define OFF_B 34816
#define SMEM1 102400   // A + fp32 C (67584)
#define SMEM2 69632    // A + fp16 C

template <int MODE>
__global__ __launch_bounds__(256, 2)
void k_gemm_wmma(const float* __restrict__ b1) {
    extern __shared__ char dyn[];

    constexpr int K      = (MODE == 1) ? 128 : 256;
    constexpr int NCHUNK = K / 128;
    constexpr int NHEADS = (MODE == 1) ? 2 : 1;
    constexpr int NCOLS  = (MODE == 1) ? 256 : 128;
    constexpr int Hstr   = (MODE == 1) ? C1 : CH;
    const __half* Asrc = (MODE == 1) ? g_axg : g_o1h;
    const __half* Bsrc = (MODE == 1) ? g_w1h : g_w2h;
    __half* Hout    = (MODE == 1) ? g_o1h : g_h2h;

    const int tid = threadIdx.x, wid = tid >> 5, lane = tid & 31;
    const int row0 = blockIdx.x * 128;
    const int warp_m = wid >> 1, warp_n = wid & 1;

    __half* AH = (__half*)(dyn + OFF_A);
    __half* BH = (__half*)(dyn + OFF_B);

    const int lr = tid >> 1, lh = tid & 1;
    const bool rok = (row0 + lr) < NN;

    for (int head = 0; head < NHEADS; head++) {
        wmma::fragment<wmma::accumulator, 16, 16, 16, float> acc[2][4];
        #pragma unroll
        for (int i = 0; i < 2; i++)
            #pragma unroll
            for (int j = 0; j < 4; j++) wmma::fill_fragment(acc[i][j], 0.f);

        #pragma unroll
        for (int c = 0; c < NCHUNK; c++) {
            if (head || c) __syncthreads();
            {
                // stage A: MODE1 per-head columns of axg; MODE2 K-chunk of o1h
                const __half* ap = (MODE == 1)
                    ? (Asrc + (size_t)(row0 + lr) * C1 + head * 128 + lh * 64)
                    : (Asrc + (size_t)(row0 + lr) * K + c * 128 + lh * 64);
                const uint4* src = (const uint4*)ap;
                uint4* dst = (uint4*)(AH + lr * PA + lh * 64);
                #pragma unroll
                for (int i = 0; i < 8; i++)
                    dst[i] = rok ? src[i] : make_uint4(0, 0, 0, 0);
            }
            {
                const uint4* src = (const uint4*)(Bsrc + (size_t)(c * 128 + lr) * NCOLS + head * 128 + lh * 64);
                uint4* dst = (uint4*)(BH + lr * PA + lh * 64);
                #pragma unroll
                for (int i = 0; i < 8; i++)
                    dst[i] = src[i];
            }
            __syncthreads();

            #pragma unroll
            for (int kk = 0; kk < 8; kk++) {
                wmma::fragment<wmma::matrix_a, 16, 16, 16, __half, wmma::row_major> af[2];
                wmma::fragment<wmma::matrix_b, 16, 16, 16, __half, wmma::row_major> bf[4];
                #pragma unroll
                for (int i = 0; i < 2; i++)
                    wmma::load_matrix_sync(af[i], AH + (warp_m * 32 + i * 16) * PA + kk * 16, PA);
                #pragma unroll
                for (int j = 0; j < 4; j++)
                    wmma::load_matrix_sync(bf[j], BH + (kk * 16) * PA + warp_n * 64 + j * 16, PA);
                #pragma unroll
                for (int i = 0; i < 2; i++)
                    #pragma unroll
                    for (int j = 0; j < 4; j++)
                        wmma::mma_sync(acc[i][j], af[i], bf[j], acc[i][j]);
            }
        }

        __syncthreads();
        if (MODE == 1) {
            // fp32 C staging; epilogue applies bias + ELU, stores fp16 o1h
            float* Cs = (float*)(dyn + OFF_B);
            #pragma unroll
            for (int i = 0; i < 2; i++)
                #pragma unroll
                for (int j = 0; j < 4; j++)
                    wmma::store_matrix_sync(Cs + (warp_m * 32 + i * 16) * PC + warp_n * 64 + j * 16,
                                            acc[i][j], PC, wmma::mem_row_major);
            __syncthreads();
            float4 bb = *(const float4*)(b1 + head * 128 + lane * 4);
            #pragma unroll 4
            for (int rr = 0; rr < 16; rr++) {
                int row = wid * 16 + rr;
                int r = row0 + row;
                float4 v = *(float4*)&Cs[row * PC + lane * 4];
                if (r < NN) {
                    uint2 pk = make_uint2(pk2(elu1(v.x + bb.x), elu1(v.y + bb.y)),
                                          pk2(elu1(v.z + bb.z), elu1(v.w + bb.w)));
                    *(uint2*)(Hout + (size_t)r * Hstr + head * 128 + lane * 4) = pk;
                }
            }
        } else {
            __half* Ch = (__half*)(dyn + OFF_B);
            #pragma unroll
            for (int i = 0; i < 2; i++)
                #pragma unroll
                for (int j = 0; j < 4; j++) {
                    wmma::fragment<wmma::accumulator, 16, 16, 16, __half> hf;
                    #pragma unroll
                    for (int e = 0; e < hf.num_elements; e++)
                        hf.x[e] = __float2half_rn(acc[i][j].x[e]);
                    wmma::store_matrix_sync(Ch + (warp_m * 32 + i * 16) * PA + warp_n * 64 + j * 16,
                                            hf, PA, wmma::mem_row_major);
                }
            __syncthreads();
            #pragma unroll
            for (int rr = 0; rr < 16; rr += 2) {
                int row = wid * 16 + rr + (lane >> 4);
                int r = row0 + row;
                uint4 v = *(const uint4*)(Ch + row * PA + (lane & 15) * 8);
                if (r < NN)
                    *(uint4*)(Hout + (size_t)r * Hstr + head * 128 + (lane & 15) * 8) = v;
            }
        }
    }
}

// ---------------- layer-2 attention dots from o1h (warp per node) ----------------
__global__ void k_dot2() {
    __shared__ float s_u2s[256], s_u2d[256];
    int tid = threadIdx.x;
    s_u2s[tid] = g_u2s[tid];
    s_u2d[tid] = g_u2d[tid];
    __syncthreads();
    int w = (blockIdx.x * blockDim.x + tid) >> 5;
    int lane = tid & 31;
    if (w >= NN) return;
    uint4 pk = *(const uint4*)(g_o1h + (size_t)w * C1 + lane * 8);
    const uint32_t* u = (const uint32_t*)&pk;
    float ds = 0.f, dd = 0.f;
    #pragma unroll
    for (int q = 0; q < 4; q++) {
        float2 f = __half22float2(*(const __half2*)&u[q]);
        int cc = lane * 8 + q * 2;
        ds += f.x * s_u2s[cc] + f.y * s_u2s[cc + 1];
        dd += f.x * s_u2d[cc] + f.y * s_u2d[cc + 1];
    }
    ds = warpSum(ds); dd = warpSum(dd);
    if (lane == 0) { g_a2s[w] = ds; g_a2d[w] = dd; }
}

// ---------------- layer-2 aggregation (4-wide) fused with MLP head ----------------
__global__ void k_agg2mlp(const float* __restrict__ b2,
                          const float* __restrict__ fc1w, const float* __restrict__ fc1b,
                          const float* __restrict__ fc2w, const float* __restrict__ fc2b,
                          float* __restrict__ out) {
    __shared__ float w1s[CH * FCH];
    __shared__ float w2s[FCH], b1s[FCH], b2s[CH];
    int tid = threadIdx.x;
    for (int i = tid; i < CH * FCH; i += blockDim.x) w1s[i] = fc1w[i];
    if (tid < FCH) { w2s[tid] = fc2w[tid]; b1s[tid] = fc1b[tid]; }
    if (tid < CH)  b2s[tid] = b2[tid];
    __syncthreads();

    int w = (blockIdx.x * blockDim.x + tid) >> 5;
    int lane = tid & 31;
    if (w >= NN) return;
    int beg = g_rowstart[w], end = g_rowstart[w + 1];
    float ad = g_a2d[w];

    float z = 0.f;
    float acc[4] = {0, 0, 0, 0};
    int j = beg;
    for (; j + 4 <= end; j += 4) {
        int s0 = g_srcs[j],     s1 = g_srcs[j + 1];
        int s2 = g_srcs[j + 2], s3 = g_srcs[j + 3];
        float a0 = g_a2s[s0], a1 = g_a2s[s1], a2 = g_a2s[s2], a3 = g_a2s[s3];
        uint2 p0 = *(const uint2*)(g_h2h + (size_t)s0 * CH + lane * 4);
        uint2 p1 = *(const uint2*)(g_h2h + (size_t)s1 * CH + lane * 4);
        uint2 p2 = *(const uint2*)(g_h2h + (size_t)s2 * CH + lane * 4);
        uint2 p3 = *(const uint2*)(g_h2h + (size_t)s3 * CH + lane * 4);
        float e0 = __expf(lrelu(a0 + ad)), e1 = __expf(lrelu(a1 + ad));
        float e2 = __expf(lrelu(a2 + ad)), e3 = __expf(lrelu(a3 + ad));
        z += (e0 + e1) + (e2 + e3);
        float2 f;
        f = __half22float2(*(const __half2*)&p0.x); acc[0] += e0 * f.x; acc[1] += e0 * f.y;
        f = __half22float2(*(const __half2*)&p0.y); acc[2] += e0 * f.x; acc[3] += e0 * f.y;
        f = __half22float2(*(const __half2*)&p1.x); acc[0] += e1 * f.x; acc[1] += e1 * f.y;
        f = __half22float2(*(const __half2*)&p1.y); acc[2] += e1 * f.x; acc[3] += e1 * f.y;
        f = __half22float2(*(const __half2*)&p2.x); acc[0] += e2 * f.x; acc[1] += e2 * f.y;
        f = __half22float2(*(const __half2*)&p2.y); acc[2] += e2 * f.x; acc[3] += e2 * f.y;
        f = __half22float2(*(const __half2*)&p3.x); acc[0] += e3 * f.x; acc[1] += e3 * f.y;
        f = __half22float2(*(const __half2*)&p3.y); acc[2] += e3 * f.x; acc[3] += e3 * f.y;
    }
    for (; j < end; j++) {
        int s = g_srcs[j];
        float e = __expf(lrelu(g_a2s[s] + ad));
        z += e;
        uint2 pk = *(const uint2*)(g_h2h + (size_t)s * CH + lane * 4);
        float2 f0 = __half22float2(*(const __half2*)&pk.x);
        float2 f1 = __half22float2(*(const __half2*)&pk.y);
        acc[0] += e * f0.x; acc[1] += e * f0.y;
        acc[2] += e * f1.x; acc[3] += e * f1.y;
    }
    float iz = 1.0f / (z + EPS);

    float hvv[4];
    #pragma unroll
    for (int q = 0; q < 4; q++) hvv[q] = elu1(acc[q] * iz + b2s[lane * 4 + q]);

    float acc0 = 0.f, acc1 = 0.f;
    #pragma unroll
    for (int k0 = 0; k0 < CH; k0 += 4) {
        int srcl = k0 >> 2;
        #pragma unroll
        for (int kk = 0; kk < 4; kk++) {
            float hk = __shfl_sync(0xffffffffu, hvv[kk], srcl);
            acc0 += hk * w1s[(k0 + kk) * FCH + lane];
            acc1 += hk * w1s[(k0 + kk) * FCH + lane + 32];
        }
    }
    float h0 = fmaxf(acc0 + b1s[lane], 0.f);
    float h1 = fmaxf(acc1 + b1s[lane + 32], 0.f);
    float p = h0 * w2s[lane] + h1 * w2s[lane + 32];
    p = warpSum(p);
    if (lane == 0) out[w] = p + fc2b[0];
}

// ---------------- launch (two-stream fork/join, graph-capturable) ----------------
extern "C" void kernel_launch(void* const* d_in, const int* in_sizes, int n_in,
                              void* d_out, int out_size) {
    const float* x    = (const float*)d_in[0];
    const int*   eraw = (const int*)d_in[1];
    const float* W1   = (const float*)d_in[2];
    const float* as1  = (const float*)d_in[3];
    const float* ad1  = (const float*)d_in[4];
    const float* b1   = (const float*)d_in[5];
    const float* W2   = (const float*)d_in[6];
    const float* as2  = (const float*)d_in[7];
    const float* ad2  = (const float*)d_in[8];
    const float* b2   = (const float*)d_in[9];
    const float* fc1w = (const float*)d_in[10];
    const float* fc1b = (const float*)d_in[11];
    const float* fc2w = (const float*)d_in[12];
    const float* fc2b = (const float*)d_in[13];
    float* out = (float*)d_out;

    static cudaStream_t s2 = nullptr;
    static cudaEvent_t evFork = nullptr, evJoin = nullptr, evO1 = nullptr, evD2 = nullptr;
    if (s2 == nullptr) {
        cudaStreamCreateWithFlags(&s2, cudaStreamNonBlocking);
        cudaEventCreateWithFlags(&evFork, cudaEventDisableTiming);
        cudaEventCreateWithFlags(&evJoin, cudaEventDisableTiming);
        cudaEventCreateWithFlags(&evO1,   cudaEventDisableTiming);
        cudaEventCreateWithFlags(&evD2,   cudaEventDisableTiming);
        cudaFuncSetAttribute(k_gemm_wmma<1>, cudaFuncAttributeMaxDynamicSharedMemorySize, SMEM1);
        cudaFuncSetAttribute(k_gemm_wmma<2>, cudaFuncAttributeMaxDynamicSharedMemorySize, SMEM2);
    }

    // stream 0: pre -> dot1 (overlaps CSR)
    k_pre<<<(PRE_TOT + 255) / 256, 256>>>(eraw, x, W1, W2, as1, ad1, as2, ad2);   // #1
    cudaEventRecord(evFork, 0);
    k_dot1<<<(NN + 7) / 8, 256>>>();                                              // #2

    // stream 2: CSR build (concurrent with dot1)
    cudaStreamWaitEvent(s2, evFork, 0);
    k_count<<<(ET + 255) / 256, 256, 0, s2>>>(eraw);                              // #3
    k_scanA<<<49, 1024, 0, s2>>>();                                               // #4
    k_scanC<<<49, 1024, 0, s2>>>();                                               // #5
    k_fill<<<(ET + 255) / 256, 256, 0, s2>>>();                                   // #6
    cudaEventRecord(evJoin, s2);

    // stream 0: aggX (needs dot1 + fill) -> GEMM-agg (o1)
    cudaStreamWaitEvent(0, evJoin, 0);
    k_aggX<<<(NN + 7) / 8, 256>>>();                                              // #7
    k_gemm_wmma<1><<<391, 256, SMEM1>>>(b1);                                      // #8
    cudaEventRecord(evO1, 0);

    // stream 2: layer-2 dots concurrent with GEMM2
    cudaStreamWaitEvent(s2, evO1, 0);
    k_dot2<<<(NN + 7) / 8, 256, 0, s2>>>();                                       // #9
    cudaEventRecord(evD2, s2);

    // stream 0: GEMM2 -> final agg + MLP
    k_gemm_wmma<2><<<391, 256, SMEM2>>>(b1);                                      // #10
    cudaStreamWaitEvent(0, evD2, 0);
    k_agg2mlp<<<(NN + 7) / 8, 256>>>(b2, fc1w, fc1b, fc2w, fc2b, out);            // #11
}

// round 17
// speedup vs baseline: 1.1743x; 1.1743x over previous
#include <cuda_runtime.h>
#include <cuda_fp16.h>
#include <mma.h>
#include <math.h>
#include <cstdint>

using namespace nvcuda;

#define NN 50000
#define NE 800000
#define ET (NE + NN)
#define C1 256
#define CH 128
#define FCH 64
#define NEG_SLOPE 0.2f
#define EPS 1e-16f

// ---------------- device scratch ----------------
__device__ int   g_is64;
__device__ int   g_deg[NN];
__device__ int   g_dinc[NN];
__device__ int   g_bsum[64];
__device__ int   g_rowstart[NN + 1];
__device__ int   g_cursor[NN];
__device__ int   g_srcs[ET];
__device__ int2  g_edge2[NE];
__device__ __half g_xh[(size_t)NN * CH];
__device__ __half g_w1h[CH * C1];
__device__ __half g_w2h[C1 * CH];
__device__ __half g_h1h[(size_t)NN * C1];
__device__ __half g_h2h[(size_t)NN * CH];
__device__ __half g_o1h[(size_t)NN * C1];
__device__ float g_a1s[NN * 2], g_a1d[NN * 2];
__device__ float g_a2s[NN],     g_a2d[NN];
__device__ float g_u1s[256], g_u1d[256];
__device__ float g_u2s[256], g_u2d[256];

// ---------------- helpers ----------------
__device__ __forceinline__ float warpSum(float v) {
    #pragma unroll
    for (int o = 16; o; o >>= 1) v += __shfl_xor_sync(0xffffffffu, v, o);
    return v;
}
__device__ __forceinline__ int warpSumI(int v) {
    #pragma unroll
    for (int o = 16; o; o >>= 1) v += __shfl_xor_sync(0xffffffffu, v, o);
    return v;
}
__device__ __forceinline__ float lrelu(float x) { return x > 0.f ? x : NEG_SLOPE * x; }
__device__ __forceinline__ float elu1(float x)  { return x > 0.f ? x : (__expf(x) - 1.0f); }
__device__ __forceinline__ uint32_t pk2(float a, float b) {
    __half2 h = __floats2half2_rn(a, b);
    return *(uint32_t*)&h;
}

// ---------------- init: zero degrees + edge width detect ----------------
__global__ void k_init(const int* __restrict__ raw) {
    int t = blockIdx.x * blockDim.x + threadIdx.x;
    if (t < NN) g_deg[t] = 0;
    if (t == 0) {
        int ok = 1;
        #pragma unroll
        for (int i = 0; i < 64; i++) ok &= (raw[2 * i + 1] == 0);
        g_is64 = ok;
    }
}

// ---------------- operand pre-conversion to fp16 ----------------
__global__ void k_prep(const float* __restrict__ x, const float* __restrict__ W1,
                       const float* __restrict__ W2) {
    const int NX  = NN * CH / 8;
    const int NW1 = CH * C1 / 8;
    const int NW2 = C1 * CH / 8;
    int t = blockIdx.x * blockDim.x + threadIdx.x;
    if (t >= NX + NW1 + NW2) return;
    const float4* src; uint4* dst; int idx;
    if (t < NX)            { src = (const float4*)x;  dst = (uint4*)g_xh;  idx = t; }
    else if (t < NX + NW1) { src = (const float4*)W1; dst = (uint4*)g_w1h; idx = t - NX; }
    else                   { src = (const float4*)W2; dst = (uint4*)g_w2h; idx = t - NX - NW1; }
    float4 a = src[2 * idx], b = src[2 * idx + 1];
    dst[idx] = make_uint4(pk2(a.x, a.y), pk2(a.z, a.w), pk2(b.x, b.y), pk2(b.z, b.w));
}

// ---------------- attention u-vectors ----------------
__global__ void k_uvec(const float* __restrict__ W1, const float* __restrict__ as1,
                       const float* __restrict__ ad1,
                       const float* __restrict__ W2, const float* __restrict__ as2,
                       const float* __restrict__ ad2) {
    int gw = (blockIdx.x * blockDim.x + threadIdx.x) >> 5;
    int lane = threadIdx.x & 31;
    if (gw < 256) {
        int h = gw >> 7, k = gw & 127;
        float4 w = ((const float4*)(W1 + k * 256 + h * 128))[lane];
        float4 s = ((const float4*)(as1 + h * 128))[lane];
        float4 d = ((const float4*)(ad1 + h * 128))[lane];
        float ps = w.x * s.x + w.y * s.y + w.z * s.z + w.w * s.w;
        float pd = w.x * d.x + w.y * d.y + w.z * d.z + w.w * d.w;
        ps = warpSum(ps); pd = warpSum(pd);
        if (lane == 0) { g_u1s[gw] = ps; g_u1d[gw] = pd; }
    } else {
        int k = gw - 256;
        float4 w = ((const float4*)(W2 + k * 128))[lane];
        float4 s = ((const float4*)as2)[lane];
        float4 d = ((const float4*)ad2)[lane];
        float ps = w.x * s.x + w.y * s.y + w.z * s.z + w.w * s.w;
        float pd = w.x * d.x + w.y * d.y + w.z * d.z + w.w * d.w;
        ps = warpSum(ps); pd = warpSum(pd);
        if (lane == 0) { g_u2s[k] = ps; g_u2d[k] = pd; }
    }
}

// ---------------- CSR build ----------------
__global__ void k_count(const int* __restrict__ raw) {
    int t = blockIdx.x * blockDim.x + threadIdx.x;
    if (t < NE) {
        int s, d;
        if (g_is64) { s = raw[2 * t]; d = raw[2 * (NE + t)]; }
        else        { s = raw[t];     d = raw[NE + t]; }
        g_edge2[t] = make_int2(s, d);
        atomicAdd(&g_deg[d], 1);
    } else if (t < ET) {
        atomicAdd(&g_deg[t - NE], 1);
    }
}
__global__ void k_scanA() {
    __shared__ int wtot[32];
    int t = threadIdx.x, lane = t & 31, wd = t >> 5;
    int i = blockIdx.x * 1024 + t;
    int v = (i < NN) ? g_deg[i] : 0;
    int ws = v;
    #pragma unroll
    for (int off = 1; off < 32; off <<= 1) {
        int y = __shfl_up_sync(0xffffffffu, ws, off);
        if (lane >= off) ws += y;
    }
    if (lane == 31) wtot[wd] = ws;
    __syncthreads();
    if (wd == 0) {
        int tv = wtot[lane];
        #pragma unroll
        for (int off = 1; off < 32; off <<= 1) {
            int y = __shfl_up_sync(0xffffffffu, tv, off);
            if (lane >= off) tv += y;
        }
        wtot[lane] = tv;
        if (lane == 31) g_bsum[blockIdx.x] = tv;
    }
    __syncthreads();
    int woff = wd ? wtot[wd - 1] : 0;
    if (i < NN) g_dinc[i] = woff + ws;
}
__global__ void k_scanC() {
    __shared__ int s_boff;
    int t = threadIdx.x;
    if (t < 32) {
        int b = blockIdx.x;
        int v = (t < b) ? g_bsum[t] : 0;
        if (t + 32 < b) v += g_bsum[t + 32];
        v = warpSumI(v);
        if (t == 0) s_boff = v;
    }
    __syncthreads();
    int boff = s_boff;
    int i = blockIdx.x * 1024 + t;
    if (i < NN) {
        int inc = g_dinc[i] + boff;
        g_rowstart[i + 1] = inc;
        g_cursor[i] = inc - g_deg[i];
    }
    if (i == 0) g_rowstart[0] = 0;
}
__global__ void k_fill() {
    int t = blockIdx.x * blockDim.x + threadIdx.x;
    if (t < NE) {
        int2 e = g_edge2[t];
        int p = atomicAdd(&g_cursor[e.y], 1);
        g_srcs[p] = e.x;
    } else if (t < ET) {
        int n = t - NE;
        int p = atomicAdd(&g_cursor[n], 1);
        g_srcs[p] = n;
    }
}

// ---------------- WMMA fp16 GEMM (R13 version) ----------------
#define PA 136
#define OFF_A 0
#define OFF_B 34816
#define SMEM_TOT 69632

template <int MODE>
__global__ __launch_bounds__(256, 2)
void k_gemm_wmma() {
    extern __shared__ char dyn[];
    __shared__ float s_u[4][128];

    constexpr int K      = (MODE == 1) ? 128 : 256;
    constexpr int NCHUNK = K / 128;
    constexpr int NHEADS = (MODE == 1) ? 2 : 1;
    constexpr int NCOLS  = (MODE == 1) ? 256 : 128;
    constexpr int Hstr   = (MODE == 1) ? C1 : CH;
    const __half* Asrc = (MODE == 1) ? g_xh : g_o1h;
    const __half* Bsrc = (MODE == 1) ? g_w1h : g_w2h;
    __half* Hout    = (MODE == 1) ? g_h1h : g_h2h;

    const int tid = threadIdx.x, wid = tid >> 5, lane = tid & 31;
    const int row0 = blockIdx.x * 128;
    const int warp_m = wid >> 1, warp_n = wid & 1;

    __half* AH = (__half*)(dyn + OFF_A);
    __half* BH = (__half*)(dyn + OFF_B);

    if (MODE == 1 && tid < 128) {
        s_u[0][tid] = g_u1s[tid];
        s_u[1][tid] = g_u1d[tid];
        s_u[2][tid] = g_u1s[128 + tid];
        s_u[3][tid] = g_u1d[128 + tid];
    }

    const int lr = tid >> 1, lh = tid & 1;
    const bool rok = (row0 + lr) < NN;

    for (int head = 0; head < NHEADS; head++) {
        wmma::fragment<wmma::accumulator, 16, 16, 16, float> acc[2][4];
        #pragma unroll
        for (int i = 0; i < 2; i++)
            #pragma unroll
            for (int j = 0; j < 4; j++) wmma::fill_fragment(acc[i][j], 0.f);

        #pragma unroll
        for (int c = 0; c < NCHUNK; c++) {
            if (head || c) __syncthreads();
            if (head == 0) {
                const uint4* src = (const uint4*)(Asrc + (size_t)(row0 + lr) * K + c * 128 + lh * 64);
                uint4* dst = (uint4*)(AH + lr * PA + lh * 64);
                #pragma unroll
                for (int i = 0; i < 8; i++)
                    dst[i] = rok ? src[i] : make_uint4(0, 0, 0, 0);
            }
            {
                const uint4* src = (const uint4*)(Bsrc + (size_t)(c * 128 + lr) * NCOLS + head * 128 + lh * 64);
                uint4* dst = (uint4*)(BH + lr * PA + lh * 64);
                #pragma unroll
                for (int i = 0; i < 8; i++)
                    dst[i] = src[i];
            }
            __syncthreads();

            if (MODE == 1 && head == 0 && c == 0) {
                const uint4* arow = (const uint4*)(AH + lr * PA + lh * 64);
                float ps0 = 0.f, pd0 = 0.f, ps1 = 0.f, pd1 = 0.f;
                #pragma unroll
                for (int i = 0; i < 8; i++) {
                    uint4 pk = arow[i];
                    const uint32_t uu[4] = {pk.x, pk.y, pk.z, pk.w};
                    #pragma unroll
                    for (int q = 0; q < 4; q++) {
                        float2 f = __half22float2(*(const __half2*)&uu[q]);
                        int kk = lh * 64 + i * 8 + q * 2;
                        ps0 += f.x * s_u[0][kk] + f.y * s_u[0][kk + 1];
                        pd0 += f.x * s_u[1][kk] + f.y * s_u[1][kk + 1];
                        ps1 += f.x * s_u[2][kk] + f.y * s_u[2][kk + 1];
                        pd1 += f.x * s_u[3][kk] + f.y * s_u[3][kk + 1];
                    }
                }
                ps0 += __shfl_xor_sync(0xffffffffu, ps0, 1);
                pd0 += __shfl_xor_sync(0xffffffffu, pd0, 1);
                ps1 += __shfl_xor_sync(0xffffffffu, ps1, 1);
                pd1 += __shfl_xor_sync(0xffffffffu, pd1, 1);
                int r = row0 + lr;
                if (lh == 0 && r < NN) {
                    g_a1s[2 * r]     = ps0; g_a1d[2 * r]     = pd0;
                    g_a1s[2 * r + 1] = ps1; g_a1d[2 * r + 1] = pd1;
                }
            }

            #pragma unroll
            for (int kk = 0; kk < 8; kk++) {
                wmma::fragment<wmma::matrix_a, 16, 16, 16, __half, wmma::row_major> af[2];
                wmma::fragment<wmma::matrix_b, 16, 16, 16, __half, wmma::row_major> bf[4];
                #pragma unroll
                for (int i = 0; i < 2; i++)
                    wmma::load_matrix_sync(af[i], AH + (warp_m * 32 + i * 16) * PA + kk * 16, PA);
                #pragma unroll
                for (int j = 0; j < 4; j++)
                    wmma::load_matrix_sync(bf[j], BH + (kk * 16) * PA + warp_n * 64 + j * 16, PA);
                #pragma unroll
                for (int i = 0; i < 2; i++)
                    #pragma unroll
                    for (int j = 0; j < 4; j++)
                        wmma::mma_sync(acc[i][j], af[i], bf[j], acc[i][j]);
            }
        }

        __syncthreads();
        __half* Ch = (__half*)(dyn + OFF_B);
        #pragma unroll
        for (int i = 0; i < 2; i++)
            #pragma unroll
            for (int j = 0; j < 4; j++) {
                wmma::fragment<wmma::accumulator, 16, 16, 16, __half> hf;
                #pragma unroll
                for (int e = 0; e < hf.num_elements; e++)
                    hf.x[e] = __float2half_rn(acc[i][j].x[e]);
                wmma::store_matrix_sync(Ch + (warp_m * 32 + i * 16) * PA + warp_n * 64 + j * 16,
                                        hf, PA, wmma::mem_row_major);
            }
        __syncthreads();

        #pragma unroll
        for (int rr = 0; rr < 16; rr += 2) {
            int row = wid * 16 + rr + (lane >> 4);
            int r = row0 + row;
            uint4 v = *(const uint4*)(Ch + row * PA + (lane & 15) * 8);
            if (r < NN)
                *(uint4*)(Hout + (size_t)r * Hstr + head * 128 + (lane & 15) * 8) = v;
        }
    }
}

// ---------------- single-pass aggregation + layer-2 dots (R13 version) ----------------
__global__ void k_agg1(const float* __restrict__ b1) {
    __shared__ float s_u2s[256], s_u2d[256];
    int tid = threadIdx.x;
    s_u2s[tid] = g_u2s[tid];
    s_u2d[tid] = g_u2d[tid];
    __syncthreads();

    int w = (blockIdx.x * blockDim.x + tid) >> 5;
    int lane = tid & 31;
    if (w >= NN) return;
    int beg = g_rowstart[w], end = g_rowstart[w + 1];

    const int hd = lane >> 4;
    const float ad = g_a1d[2 * w + hd];

    float z = 0.f;
    float acc[8] = {0, 0, 0, 0, 0, 0, 0, 0};
    int j = beg;
    for (; j + 4 <= end; j += 4) {
        int s0 = g_srcs[j],     s1 = g_srcs[j + 1];
        int s2 = g_srcs[j + 2], s3 = g_srcs[j + 3];
        float a0 = g_a1s[2 * s0 + hd], a1 = g_a1s[2 * s1 + hd];
        float a2 = g_a1s[2 * s2 + hd], a3 = g_a1s[2 * s3 + hd];
        uint4 p0 = *(const uint4*)(g_h1h + (size_t)s0 * C1 + lane * 8);
        uint4 p1 = *(const uint4*)(g_h1h + (size_t)s1 * C1 + lane * 8);
        uint4 p2 = *(const uint4*)(g_h1h + (size_t)s2 * C1 + lane * 8);
        uint4 p3 = *(const uint4*)(g_h1h + (size_t)s3 * C1 + lane * 8);
        float e0 = __expf(lrelu(a0 + ad)), e1 = __expf(lrelu(a1 + ad));
        float e2 = __expf(lrelu(a2 + ad)), e3 = __expf(lrelu(a3 + ad));
        z += (e0 + e1) + (e2 + e3);
        const uint32_t* u0 = (const uint32_t*)&p0;
        const uint32_t* u1 = (const uint32_t*)&p1;
        const uint32_t* u2 = (const uint32_t*)&p2;
        const uint32_t* u3 = (const uint32_t*)&p3;
        #pragma unroll
        for (int q = 0; q < 4; q++) {
            float2 f0 = __half22float2(*(const __half2*)&u0[q]);
            float2 f1 = __half22float2(*(const __half2*)&u1[q]);
            float2 f2 = __half22float2(*(const __half2*)&u2[q]);
            float2 f3 = __half22float2(*(const __half2*)&u3[q]);
            acc[2 * q]     += e0 * f0.x + e1 * f1.x + e2 * f2.x + e3 * f3.x;
            acc[2 * q + 1] += e0 * f0.y + e1 * f1.y + e2 * f2.y + e3 * f3.y;
        }
    }
    for (; j < end; j++) {
        int s = g_srcs[j];
        float e = __expf(lrelu(g_a1s[2 * s + hd] + ad));
        z += e;
        uint4 pk = *(const uint4*)(g_h1h + (size_t)s * C1 + lane * 8);
        const uint32_t* u = (const uint32_t*)&pk;
        #pragma unroll
        for (int q = 0; q < 4; q++) {
            float2 f = __half22float2(*(const __half2*)&u[q]);
            acc[2 * q]     += e * f.x;
            acc[2 * q + 1] += e * f.y;
        }
    }
    float iz = 1.0f / (z + EPS);
    const float* bb = b1 + lane * 8;
    float ov[8];
    #pragma unroll
    for (int q = 0; q < 8; q++) ov[q] = elu1(acc[q] * iz + bb[q]);
    uint4 o;
    o.x = pk2(ov[0], ov[1]);
    o.y = pk2(ov[2], ov[3]);
    o.z = pk2(ov[4], ov[5]);
    o.w = pk2(ov[6], ov[7]);
    *(uint4*)(g_o1h + (size_t)w * C1 + lane * 8) = o;

    float ds = 0.f, dd = 0.f;
    const uint32_t* op = (const uint32_t*)&o;
    #pragma unroll
    for (int q = 0; q < 4; q++) {
        float2 f = __half22float2(*(const __half2*)&op[q]);
        int cc = lane * 8 + q * 2;
        ds += f.x * s_u2s[cc] + f.y * s_u2s[cc + 1];
        dd += f.x * s_u2d[cc] + f.y * s_u2d[cc + 1];
    }
    ds = warpSum(ds); dd = warpSum(dd);
    if (lane == 0) { g_a2s[w] = ds; g_a2d[w] = dd; }
}

// ---------------- layer-2 aggregation + MLP head (grid-stride persistent) ----------------
#define AGG2_BLOCKS 1184
__global__ void k_agg2mlp(const float* __restrict__ b2,
                          const float* __restrict__ fc1w, const float* __restrict__ fc1b,
                          const float* __restrict__ fc2w, const float* __restrict__ fc2b,
                          float* __restrict__ out) {
    __shared__ float w1s[CH * FCH];
    __shared__ float w2s[FCH], b1s[FCH], b2s[CH];
    int tid = threadIdx.x;
    for (int i = tid; i < CH * FCH; i += blockDim.x) w1s[i] = fc1w[i];
    if (tid < FCH) { w2s[tid] = fc2w[tid]; b1s[tid] = fc1b[tid]; }
    if (tid < CH)  b2s[tid] = b2[tid];
    __syncthreads();

    int lane = tid & 31;
    const int wstep = (AGG2_BLOCKS * 256) >> 5;
    for (int w = (blockIdx.x * blockDim.x + tid) >> 5; w < NN; w += wstep) {
        int beg = g_rowstart[w], end = g_rowstart[w + 1];
        float ad = g_a2d[w];

        float z = 0.f;
        float acc[4] = {0, 0, 0, 0};
        int j = beg;
        for (; j + 4 <= end; j += 4) {
            int s0 = g_srcs[j],     s1 = g_srcs[j + 1];
            int s2 = g_srcs[j + 2], s3 = g_srcs[j + 3];
            float a0 = g_a2s[s0], a1 = g_a2s[s1], a2 = g_a2s[s2], a3 = g_a2s[s3];
            uint2 p0 = *(const uint2*)(g_h2h + (size_t)s0 * CH + lane * 4);
            uint2 p1 = *(const uint2*)(g_h2h + (size_t)s1 * CH + lane * 4);
            uint2 p2 = *(const uint2*)(g_h2h + (size_t)s2 * CH + lane * 4);
            uint2 p3 = *(const uint2*)(g_h2h + (size_t)s3 * CH + lane * 4);
            float e0 = __expf(lrelu(a0 + ad)), e1 = __expf(lrelu(a1 + ad));
            float e2 = __expf(lrelu(a2 + ad)), e3 = __expf(lrelu(a3 + ad));
            z += (e0 + e1) + (e2 + e3);
            float2 f;
            f = __half22float2(*(const __half2*)&p0.x); acc[0] += e0 * f.x; acc[1] += e0 * f.y;
            f = __half22float2(*(const __half2*)&p0.y); acc[2] += e0 * f.x; acc[3] += e0 * f.y;
            f = __half22float2(*(const __half2*)&p1.x); acc[0] += e1 * f.x; acc[1] += e1 * f.y;
            f = __half22float2(*(const __half2*)&p1.y); acc[2] += e1 * f.x; acc[3] += e1 * f.y;
            f = __half22float2(*(const __half2*)&p2.x); acc[0] += e2 * f.x; acc[1] += e2 * f.y;
            f = __half22float2(*(const __half2*)&p2.y); acc[2] += e2 * f.x; acc[3] += e2 * f.y;
            f = __half22float2(*(const __half2*)&p3.x); acc[0] += e3 * f.x; acc[1] += e3 * f.y;
            f = __half22float2(*(const __half2*)&p3.y); acc[2] += e3 * f.x; acc[3] += e3 * f.y;
        }
        for (; j < end; j++) {
            int s = g_srcs[j];
            float e = __expf(lrelu(g_a2s[s] + ad));
            z += e;
            uint2 pk = *(const uint2*)(g_h2h + (size_t)s * CH + lane * 4);
            float2 f0 = __half22float2(*(const __half2*)&pk.x);
            float2 f1 = __half22float2(*(const __half2*)&pk.y);
            acc[0] += e * f0.x; acc[1] += e * f0.y;
            acc[2] += e * f1.x; acc[3] += e * f1.y;
        }
        float iz = 1.0f / (z + EPS);

        float hvv[4];
        #pragma unroll
        for (int q = 0; q < 4; q++) hvv[q] = elu1(acc[q] * iz + b2s[lane * 4 + q]);

        float acc0 = 0.f, acc1 = 0.f;
        #pragma unroll
        for (int k0 = 0; k0 < CH; k0 += 4) {
            int srcl = k0 >> 2;
            #pragma unroll
            for (int kk = 0; kk < 4; kk++) {
                float hk = __shfl_sync(0xffffffffu, hvv[kk], srcl);
                acc0 += hk * w1s[(k0 + kk) * FCH + lane];
                acc1 += hk * w1s[(k0 + kk) * FCH + lane + 32];
            }
        }
        float h0 = fmaxf(acc0 + b1s[lane], 0.f);
        float h1 = fmaxf(acc1 + b1s[lane + 32], 0.f);
        float p = h0 * w2s[lane] + h1 * w2s[lane + 32];
        p = warpSum(p);
        if (lane == 0) out[w] = p + fc2b[0];
    }
}

// ---------------- launch (R13 two-stream fork/join schedule) ----------------
extern "C" void kernel_launch(void* const* d_in, const int* in_sizes, int n_in,
                              void* d_out, int out_size) {
    const float* x    = (const float*)d_in[0];
    const int*   eraw = (const int*)d_in[1];
    const float* W1   = (const float*)d_in[2];
    const float* as1  = (const float*)d_in[3];
    const float* ad1  = (const float*)d_in[4];
    const float* b1   = (const float*)d_in[5];
    const float* W2   = (const float*)d_in[6];
    const float* as2  = (const float*)d_in[7];
    const float* ad2  = (const float*)d_in[8];
    const float* b2   = (const float*)d_in[9];
    const float* fc1w = (const float*)d_in[10];
    const float* fc1b = (const float*)d_in[11];
    const float* fc2w = (const float*)d_in[12];
    const float* fc2b = (const float*)d_in[13];
    float* out = (float*)d_out;

    static cudaStream_t s2 = nullptr;
    static cudaEvent_t evFork = nullptr, evJoin = nullptr;
    if (s2 == nullptr) {
        cudaStreamCreateWithFlags(&s2, cudaStreamNonBlocking);
        cudaEventCreateWithFlags(&evFork, cudaEventDisableTiming);
        cudaEventCreateWithFlags(&evJoin, cudaEventDisableTiming);
        cudaFuncSetAttribute(k_gemm_wmma<1>, cudaFuncAttributeMaxDynamicSharedMemorySize, SMEM_TOT);
        cudaFuncSetAttribute(k_gemm_wmma<2>, cudaFuncAttributeMaxDynamicSharedMemorySize, SMEM_TOT);
    }

    const int NPREP = NN * CH / 8 + CH * C1 / 8 + C1 * CH / 8;

    // stream 0: init -> prep -> uvec -> GEMM1
    k_init<<<(NN + 255) / 256, 256>>>(eraw);                       // #1
    cudaEventRecord(evFork, 0);
    k_prep<<<(NPREP + 255) / 256, 256>>>(x, W1, W2);               // #2
    k_uvec<<<64, 256>>>(W1, as1, ad1, W2, as2, ad2);               // #3
    k_gemm_wmma<1><<<391, 256, SMEM_TOT>>>();                      // #4 -> ncu window

    // stream 2 (forked after init): CSR build, concurrent with GEMM1 path
    cudaStreamWaitEvent(s2, evFork, 0);
    k_count<<<(ET + 255) / 256, 256, 0, s2>>>(eraw);               // #5
    k_scanA<<<49, 1024, 0, s2>>>();                                // #6
    k_scanC<<<49, 1024, 0, s2>>>();                                // #7
    k_fill<<<(ET + 255) / 256, 256, 0, s2>>>();                    // #8
    cudaEventRecord(evJoin, s2);

    // join: agg1 needs GEMM1 (program order) + fill (event)
    cudaStreamWaitEvent(0, evJoin, 0);
    k_agg1<<<(NN + 7) / 8, 256>>>(b1);                             // #9
    k_gemm_wmma<2><<<391, 256, SMEM_TOT>>>();                      // #10
    k_agg2mlp<<<AGG2_BLOCKS, 256>>>(b2, fc1w, fc1b, fc2w, fc2b, out);  // #11
}